// round 11
// baseline (speedup 1.0000x reference)
#include <cuda_runtime.h>
#include <math.h>
#include <stdint.h>

#define N_NODES 20000
#define N_EDGES 640000
#define FIN     256
#define HDIM    512
#define KTOP    1000
#define NSORT   32768   // next pow2 >= N_NODES

// ---------------- scratch (device globals; no allocation allowed) ----------
__device__ float g_x[(size_t)N_NODES * HDIM];   // layer output / GEMM2 out
__device__ float g_h[(size_t)N_NODES * HDIM];   // x + agg
__device__ float g_t[(size_t)N_NODES * HDIM];   // relu(h@w1+b1)
__device__ float g_o1[N_NODES * 2];
__device__ float g_o2[N_NODES * 2];
__device__ float g_dist[NSORT];
__device__ int   g_deg[N_NODES];
__device__ int   g_rowptr[N_NODES + 1];
__device__ int   g_cursor[N_NODES + 1];
__device__ int   g_csrsrc[N_EDGES];

// ---------------- CSR build (counting sort by dst) --------------------------
__global__ __launch_bounds__(256) void zero_deg_kernel() {
    int i = blockIdx.x * blockDim.x + threadIdx.x;
    if (i < N_NODES) g_deg[i] = 0;
}

__global__ __launch_bounds__(256) void hist_kernel(const int* __restrict__ dst) {
    int e = blockIdx.x * blockDim.x + threadIdx.x;
    if (e < N_EDGES) atomicAdd(&g_deg[dst[e]], 1);
}

// single block, 256 threads: exclusive scan of g_deg -> g_rowptr, g_cursor
__global__ __launch_bounds__(256) void scan_kernel() {
    __shared__ int sc[256];
    const int CH = 79;  // 256*79 = 20224 >= 20001
    int tid = threadIdx.x;
    int base = tid * CH;
    int ssum = 0;
    for (int i = 0; i < CH; i++) {
        int idx = base + i;
        if (idx < N_NODES) ssum += g_deg[idx];
    }
    sc[tid] = ssum;
    __syncthreads();
    for (int off = 1; off < 256; off <<= 1) {
        int v = 0;
        if (tid >= off) v = sc[tid - off];
        __syncthreads();
        sc[tid] += v;
        __syncthreads();
    }
    int off = (tid == 0) ? 0 : sc[tid - 1];
    for (int i = 0; i < CH; i++) {
        int idx = base + i;
        if (idx <= N_NODES) {
            g_rowptr[idx] = off;
            g_cursor[idx] = off;
            if (idx < N_NODES) off += g_deg[idx];
        }
    }
}

__global__ __launch_bounds__(256) void fill_kernel(const int* __restrict__ src,
                                                   const int* __restrict__ dst) {
    int e = blockIdx.x * blockDim.x + threadIdx.x;
    if (e < N_EDGES) {
        int d = dst[e];
        int p = atomicAdd(&g_cursor[d], 1);
        g_csrsrc[p] = src[e];
    }
}

// ---------------- aggregation: h[dst] = x[dst] + sum_{src->dst} x[src] ------
__global__ __launch_bounds__(128) void agg512_kernel(const float* __restrict__ xin,
                                                     float* __restrict__ hout) {
    int node = blockIdx.x;
    int tid  = threadIdx.x;   // 128 threads, one float4 each (512 floats/row)
    const float4* __restrict__ xv = (const float4*)xin;
    float4 acc = xv[(size_t)node * 128 + tid];
    int s = g_rowptr[node], e = g_rowptr[node + 1];
#pragma unroll 4
    for (int i = s; i < e; i++) {
        int sr = g_csrsrc[i];
        float4 r = xv[(size_t)sr * 128 + tid];
        acc.x += r.x; acc.y += r.y; acc.z += r.z; acc.w += r.w;
    }
    ((float4*)hout)[(size_t)node * 128 + tid] = acc;
}

__global__ __launch_bounds__(128) void agg256_kernel(const float* __restrict__ xin,
                                                     float* __restrict__ hout) {
    int node = blockIdx.x;
    int tid  = threadIdx.x;   // 128 threads, one float2 each (256 floats/row)
    const float2* __restrict__ xv = (const float2*)xin;
    float2 acc = xv[(size_t)node * 128 + tid];
    int s = g_rowptr[node], e = g_rowptr[node + 1];
#pragma unroll 4
    for (int i = s; i < e; i++) {
        int sr = g_csrsrc[i];
        float2 r = xv[(size_t)sr * 128 + tid];
        acc.x += r.x; acc.y += r.y;
    }
    ((float2*)hout)[(size_t)node * 128 + tid] = acc;
}

// ---------------- tiled fp32 GEMM: C = act(A[R,K] @ W[K,M] + bias) ----------
#define BM 128
#define BN 64
#define BK 8
#define TM 8
#define TN 4

__global__ __launch_bounds__(256) void gemm_bias_act_kernel(
    const float* __restrict__ A, const float* __restrict__ W,
    const float* __restrict__ bias, float* __restrict__ C,
    int R, int K, int M, int doRelu)
{
    __shared__ float As[BK][BM];
    __shared__ float Bs[BK][BN];

    int tid = threadIdx.x;
    int tx = tid & 15;   // 16 col-groups * TN = 64
    int ty = tid >> 4;   // 16 row-groups * TM = 128
    int rowBase = blockIdx.x * BM;
    int colBase = blockIdx.y * BN;

    float acc[TM][TN];
#pragma unroll
    for (int i = 0; i < TM; i++)
#pragma unroll
        for (int j = 0; j < TN; j++) acc[i][j] = 0.f;

    int lrow = tid >> 1;       // 0..127
    int lseg = tid & 1;        // 0..1  (two float4 per 8-wide row)

    for (int k0 = 0; k0 < K; k0 += BK) {
        // load A tile [BM x BK] (row-major, 8 contiguous floats per row)
        int ar = rowBase + lrow;
        float4 av = make_float4(0.f, 0.f, 0.f, 0.f);
        if (ar < R) av = *(const float4*)(A + (size_t)ar * K + k0 + lseg * 4);
        As[lseg * 4 + 0][lrow] = av.x;
        As[lseg * 4 + 1][lrow] = av.y;
        As[lseg * 4 + 2][lrow] = av.z;
        As[lseg * 4 + 3][lrow] = av.w;
        // load B tile [BK x BN]
        {
            int idx = tid;
            int bk = idx >> 6, bc = idx & 63;
            Bs[bk][bc] = W[(size_t)(k0 + bk) * M + colBase + bc];
            idx = tid + 256;
            bk = idx >> 6; bc = idx & 63;
            Bs[bk][bc] = W[(size_t)(k0 + bk) * M + colBase + bc];
        }
        __syncthreads();

#pragma unroll
        for (int kk = 0; kk < BK; kk++) {
            float4 a0 = *(const float4*)&As[kk][ty * TM];
            float4 a1 = *(const float4*)&As[kk][ty * TM + 4];
            float4 b  = *(const float4*)&Bs[kk][tx * TN];
            float ra[TM] = {a0.x, a0.y, a0.z, a0.w, a1.x, a1.y, a1.z, a1.w};
            float rb[TN] = {b.x, b.y, b.z, b.w};
#pragma unroll
            for (int i = 0; i < TM; i++)
#pragma unroll
                for (int j = 0; j < TN; j++) acc[i][j] += ra[i] * rb[j];
        }
        __syncthreads();
    }

    float4 bv = *(const float4*)(bias + colBase + tx * TN);
#pragma unroll
    for (int i = 0; i < TM; i++) {
        int r = rowBase + ty * TM + i;
        if (r < R) {
            float4 o;
            o.x = acc[i][0] + bv.x;
            o.y = acc[i][1] + bv.y;
            o.z = acc[i][2] + bv.z;
            o.w = acc[i][3] + bv.w;
            if (doRelu) {
                o.x = fmaxf(o.x, 0.f); o.y = fmaxf(o.y, 0.f);
                o.z = fmaxf(o.z, 0.f); o.w = fmaxf(o.w, 0.f);
            }
            *(float4*)(C + (size_t)r * M + colBase + tx * TN) = o;
        }
    }
}

// ---------------- final linear [N,512] -> [N,2] -----------------------------
__global__ __launch_bounds__(256) void lin_kernel(const float* __restrict__ x,
                                                  const float* __restrict__ lw,
                                                  const float* __restrict__ lb,
                                                  float* __restrict__ o)
{
    int gw   = (blockIdx.x * blockDim.x + threadIdx.x) >> 5;
    int lane = threadIdx.x & 31;
    if (gw >= N_NODES) return;
    const float* __restrict__ row = x + (size_t)gw * HDIM;
    float a0 = 0.f, a1 = 0.f;
#pragma unroll 4
    for (int k = lane; k < HDIM; k += 32) {
        float v = row[k];
        a0 += v * lw[2 * k];
        a1 += v * lw[2 * k + 1];
    }
#pragma unroll
    for (int off = 16; off; off >>= 1) {
        a0 += __shfl_down_sync(0xffffffffu, a0, off);
        a1 += __shfl_down_sync(0xffffffffu, a1, off);
    }
    if (lane == 0) {
        o[gw * 2 + 0] = a0 + lb[0];
        o[gw * 2 + 1] = a1 + lb[1];
    }
}

// ---------------- pairwise distance -----------------------------------------
__global__ __launch_bounds__(256) void dist_kernel() {
    int i = blockIdx.x * blockDim.x + threadIdx.x;
    if (i >= NSORT) return;
    if (i < N_NODES) {
        float d0 = g_o1[2 * i]     - g_o2[2 * i]     + 1e-6f;
        float d1 = g_o1[2 * i + 1] - g_o2[2 * i + 1] + 1e-6f;
        g_dist[i] = sqrtf(d0 * d0 + d1 * d1);
    } else {
        g_dist[i] = -1.0f;   // dist >= 0, so -1 never reaches top-k
    }
}

// ---------------- top-k (bitonic sort) + MLP head, single block --------------
#define HTHREADS 512

__global__ __launch_bounds__(HTHREADS, 1)
void head_kernel(const float* __restrict__ fc1w, const float* __restrict__ fc1b,
                 const float* __restrict__ ln1g, const float* __restrict__ ln1b,
                 const float* __restrict__ fc2w, const float* __restrict__ fc2b,
                 const float* __restrict__ ln2g, const float* __restrict__ ln2b,
                 const float* __restrict__ fc3w, const float* __restrict__ fc3b,
                 float* __restrict__ out)
{
    extern __shared__ float sm[];
    float* s    = sm;                  // NSORT
    float* red  = sm + NSORT;          // 512 (fc1 partials: 4*128)
    float* h1   = red + 512;           // 128
    float* h2   = h1 + 128;            // 512
    float* misc = h2 + 512;            // 4

    int tid = threadIdx.x;

    for (int i = tid; i < NSORT; i += HTHREADS) s[i] = g_dist[i];
    __syncthreads();

    // ascending bitonic sort
    for (int k = 2; k <= NSORT; k <<= 1) {
        for (int j = k >> 1; j > 0; j >>= 1) {
            for (int i = tid; i < NSORT; i += HTHREADS) {
                int ixj = i ^ j;
                if (ixj > i) {
                    float a = s[i], b = s[ixj];
                    bool up = ((i & k) == 0);
                    if (up ? (a > b) : (a < b)) { s[i] = b; s[ixj] = a; }
                }
            }
            __syncthreads();
        }
    }
    // vals[r] = s[NSORT-1-r]  (descending top-k)

    // fc1: h1[j] = sum_r vals[r] * fc1w[r,j] + fc1b[j]     (K=1000 -> 128)
    {
        int part = tid >> 7;   // 0..3
        int j    = tid & 127;
        float acc = 0.f;
        for (int r = part; r < KTOP; r += 4)
            acc += s[NSORT - 1 - r] * fc1w[r * 128 + j];
        red[part * 128 + j] = acc;
    }
    __syncthreads();
    if (tid < 128) {
        float v = fc1b[tid];
        for (int p = 0; p < 4; p++) v += red[p * 128 + tid];
        h1[tid] = v;
    }
    __syncthreads();
    if (tid == 0) {
        float m = 0.f;
        for (int i = 0; i < 128; i++) m += h1[i];
        m /= 128.f;
        float v = 0.f;
        for (int i = 0; i < 128; i++) { float d = h1[i] - m; v += d * d; }
        v /= 128.f;
        misc[0] = m;
        misc[1] = rsqrtf(v + 1e-5f);
    }
    __syncthreads();
    if (tid < 128) {
        float v = (h1[tid] - misc[0]) * misc[1] * ln1g[tid] + ln1b[tid];
        h1[tid] = fmaxf(v, 0.f);
    }
    __syncthreads();

    // fc2: 128 -> 512   (one output per thread)
    {
        float acc = fc2b[tid];
        for (int k = 0; k < 128; k++) acc += h1[k] * fc2w[k * 512 + tid];
        h2[tid] = acc;
    }
    __syncthreads();
    if (tid == 0) {
        float m = 0.f;
        for (int i = 0; i < 512; i++) m += h2[i];
        m /= 512.f;
        float v = 0.f;
        for (int i = 0; i < 512; i++) { float d = h2[i] - m; v += d * d; }
        v /= 512.f;
        misc[0] = m;
        misc[1] = rsqrtf(v + 1e-5f);
    }
    __syncthreads();
    {
        float v = (h2[tid] - misc[0]) * misc[1] * ln2g[tid] + ln2b[tid];
        red[tid] = fmaxf(v, 0.f) * fc3w[tid];
    }
    __syncthreads();
    if (tid == 0) {
        float z = fc3b[0];
        for (int i = 0; i < 512; i++) z += red[i];
        out[0] = 1.f / (1.f + expf(-z));
    }
}

// ---------------- launcher ---------------------------------------------------
extern "C" void kernel_launch(void* const* d_in, const int* in_sizes, int n_in,
                              void* d_out, int out_size)
{
    (void)in_sizes; (void)n_in; (void)out_size;
    const float* x1   = (const float*)d_in[0];
    const int*   ei1  = (const int*)  d_in[1];
    const float* x2   = (const float*)d_in[2];
    const int*   ei2  = (const int*)  d_in[3];
    const float* w11  = (const float*)d_in[4];
    const float* b11  = (const float*)d_in[5];
    const float* w12  = (const float*)d_in[6];
    const float* b12  = (const float*)d_in[7];
    const float* w21  = (const float*)d_in[8];
    const float* b21  = (const float*)d_in[9];
    const float* w22  = (const float*)d_in[10];
    const float* b22  = (const float*)d_in[11];
    const float* w31  = (const float*)d_in[12];
    const float* b31  = (const float*)d_in[13];
    const float* w32  = (const float*)d_in[14];
    const float* b32  = (const float*)d_in[15];
    const float* linw = (const float*)d_in[16];
    const float* linb = (const float*)d_in[17];
    const float* fc1w = (const float*)d_in[18];
    const float* fc1b = (const float*)d_in[19];
    const float* ln1g = (const float*)d_in[20];
    const float* ln1b = (const float*)d_in[21];
    const float* fc2w = (const float*)d_in[22];
    const float* fc2b = (const float*)d_in[23];
    const float* ln2g = (const float*)d_in[24];
    const float* ln2b = (const float*)d_in[25];
    const float* fc3w = (const float*)d_in[26];
    const float* fc3b = (const float*)d_in[27];
    float* out = (float*)d_out;

    float *p_x, *p_h, *p_t, *p_o1, *p_o2;
    cudaGetSymbolAddress((void**)&p_x,  g_x);
    cudaGetSymbolAddress((void**)&p_h,  g_h);
    cudaGetSymbolAddress((void**)&p_t,  g_t);
    cudaGetSymbolAddress((void**)&p_o1, g_o1);
    cudaGetSymbolAddress((void**)&p_o2, g_o2);

    dim3 gemm_grid((N_NODES + BM - 1) / BM, HDIM / BN);
    int eblk = (N_EDGES + 255) / 256;
    int nblk = (N_NODES + 255) / 256;

    const float* Xs[2]  = {x1, x2};
    const int*   EIs[2] = {ei1, ei2};
    float*       Os[2]  = {p_o1, p_o2};

    for (int g = 0; g < 2; g++) {
        const int* src = EIs[g];
        const int* dst = EIs[g] + N_EDGES;

        // CSR build
        zero_deg_kernel<<<nblk, 256>>>();
        hist_kernel<<<eblk, 256>>>(dst);
        scan_kernel<<<1, 256>>>();
        fill_kernel<<<eblk, 256>>>(src, dst);

        // layer 1 (FIN=256 input)
        agg256_kernel<<<N_NODES, 128>>>(Xs[g], p_h);
        gemm_bias_act_kernel<<<gemm_grid, 256>>>(p_h, w11, b11, p_t, N_NODES, FIN,  HDIM, 1);
        gemm_bias_act_kernel<<<gemm_grid, 256>>>(p_t, w12, b12, p_x, N_NODES, HDIM, HDIM, 1);
        // layer 2
        agg512_kernel<<<N_NODES, 128>>>(p_x, p_h);
        gemm_bias_act_kernel<<<gemm_grid, 256>>>(p_h, w21, b21, p_t, N_NODES, HDIM, HDIM, 1);
        gemm_bias_act_kernel<<<gemm_grid, 256>>>(p_t, w22, b22, p_x, N_NODES, HDIM, HDIM, 1);
        // layer 3
        agg512_kernel<<<N_NODES, 128>>>(p_x, p_h);
        gemm_bias_act_kernel<<<gemm_grid, 256>>>(p_h, w31, b31, p_t, N_NODES, HDIM, HDIM, 1);
        gemm_bias_act_kernel<<<gemm_grid, 256>>>(p_t, w32, b32, p_x, N_NODES, HDIM, HDIM, 1);
        // lin -> [N,2]
        lin_kernel<<<(N_NODES * 32 + 255) / 256, 256>>>(p_x, linw, linb, Os[g]);
    }

    dist_kernel<<<NSORT / 256, 256>>>();

    const int SMEM_HEAD = (NSORT + 512 + 128 + 512 + 8) * (int)sizeof(float);
    cudaFuncSetAttribute(head_kernel, cudaFuncAttributeMaxDynamicSharedMemorySize, SMEM_HEAD);
    head_kernel<<<1, HTHREADS, SMEM_HEAD>>>(fc1w, fc1b, ln1g, ln1b,
                                            fc2w, fc2b, ln2g, ln2b,
                                            fc3w, fc3b, out);
}

// round 13
// speedup vs baseline: 1.7927x; 1.7927x over previous
#include <cuda_runtime.h>
#include <cuda_bf16.h>
#include <math.h>
#include <stdint.h>

#define N_NODES 20000
#define N_EDGES 640000
#define RTOT    40000     // both graphs merged
#define FIN     256
#define HDIM    512
#define MOUT    512
#define KTOP    1000
#define NSORT   32768

// ---------------- scratch (device globals; no allocation allowed) ----------
__device__ float g_x[(size_t)RTOT * HDIM];
__device__ __nv_bfloat16 g_ahi[(size_t)RTOT * HDIM];
__device__ __nv_bfloat16 g_alo[(size_t)RTOT * HDIM];
__device__ __nv_bfloat16 g_thi[(size_t)RTOT * HDIM];
__device__ __nv_bfloat16 g_tlo[(size_t)RTOT * HDIM];
#define WTOT (512*256 + 5*512*512)
__device__ __nv_bfloat16 g_whi[WTOT];
__device__ __nv_bfloat16 g_wlo[WTOT];
__device__ float g_o1[N_NODES * 2];
__device__ float g_o2[N_NODES * 2];
__device__ float g_dist[NSORT];
__device__ int   g_deg[N_NODES];
__device__ int   g_rowptr[2 * (N_NODES + 1)];
__device__ int   g_cursor[N_NODES + 1];
__device__ int   g_csrsrc[2 * N_EDGES];

// ---------------- helpers ----------------------------------------------------
__device__ __forceinline__ uint32_t smem_u32(const void* p) {
    uint32_t a;
    asm("{ .reg .u64 t; cvta.to.shared.u64 t, %1; cvt.u32.u64 %0, t; }" : "=r"(a) : "l"(p));
    return a;
}
__device__ __forceinline__ __nv_bfloat162 bpack(__nv_bfloat16 a, __nv_bfloat16 b) {
    __nv_bfloat162 t; t.x = a; t.y = b; return t;
}
#define LDSM4(r0, r1, r2, r3, addr) \
    asm volatile("ldmatrix.sync.aligned.m8n8.x4.shared.b16 {%0,%1,%2,%3}, [%4];" \
                 : "=r"(r0), "=r"(r1), "=r"(r2), "=r"(r3) : "r"(addr))
#define LDSM2(r0, r1, addr) \
    asm volatile("ldmatrix.sync.aligned.m8n8.x2.shared.b16 {%0,%1}, [%2];" \
                 : "=r"(r0), "=r"(r1) : "r"(addr))
#define MMA16816(c, a, b) \
    asm volatile("mma.sync.aligned.m16n8k16.row.col.f32.bf16.bf16.f32 " \
                 "{%0,%1,%2,%3}, {%4,%5,%6,%7}, {%8,%9}, {%0,%1,%2,%3};" \
                 : "+f"((c)[0]), "+f"((c)[1]), "+f"((c)[2]), "+f"((c)[3]) \
                 : "r"((a)[0]), "r"((a)[1]), "r"((a)[2]), "r"((a)[3]), \
                   "r"((b)[0]), "r"((b)[1]))

// ---------------- CSR build --------------------------------------------------
__global__ __launch_bounds__(256) void zero_deg_kernel() {
    int i = blockIdx.x * blockDim.x + threadIdx.x;
    if (i < N_NODES) g_deg[i] = 0;
}
__global__ __launch_bounds__(256) void hist_kernel(const int* __restrict__ dst) {
    int e = blockIdx.x * blockDim.x + threadIdx.x;
    if (e < N_EDGES) atomicAdd(&g_deg[dst[e]], 1);
}
__global__ __launch_bounds__(256) void scan_kernel(int gsel) {
    __shared__ int sc[256];
    const int CH = 79;
    int* rp = g_rowptr + gsel * (N_NODES + 1);
    int tid = threadIdx.x;
    int base = tid * CH;
    int ssum = 0;
    for (int i = 0; i < CH; i++) {
        int idx = base + i;
        if (idx < N_NODES) ssum += g_deg[idx];
    }
    sc[tid] = ssum;
    __syncthreads();
    for (int off = 1; off < 256; off <<= 1) {
        int v = 0;
        if (tid >= off) v = sc[tid - off];
        __syncthreads();
        sc[tid] += v;
        __syncthreads();
    }
    int off = (tid == 0) ? 0 : sc[tid - 1];
    for (int i = 0; i < CH; i++) {
        int idx = base + i;
        if (idx <= N_NODES) {
            rp[idx] = off;
            g_cursor[idx] = off;
            if (idx < N_NODES) off += g_deg[idx];
        }
    }
}
__global__ __launch_bounds__(256) void fill_kernel(const int* __restrict__ src,
                                                   const int* __restrict__ dst, int gsel) {
    int e = blockIdx.x * blockDim.x + threadIdx.x;
    if (e < N_EDGES) {
        int d = dst[e];
        int p = atomicAdd(&g_cursor[d], 1);
        g_csrsrc[gsel * N_EDGES + p] = src[e];
    }
}

// ---------------- weight prep: transpose + bf16 split ------------------------
__global__ __launch_bounds__(256) void wprep_kernel(const float* __restrict__ src,
                                                    int K, int M,
                                                    __nv_bfloat16* __restrict__ dhi,
                                                    __nv_bfloat16* __restrict__ dlo) {
    int idx = blockIdx.x * blockDim.x + threadIdx.x;
    if (idx < K * M) {
        int k = idx / M, m = idx % M;
        float v = src[idx];
        __nv_bfloat16 h = __float2bfloat16(v);
        dhi[(size_t)m * K + k] = h;
        dlo[(size_t)m * K + k] = __float2bfloat16(v - __bfloat162float(h));
    }
}

// ---------------- aggregation (emits hi/lo split) ----------------------------
__global__ __launch_bounds__(128) void agg256_kernel(const float* __restrict__ x1,
                                                     const float* __restrict__ x2) {
    int node = blockIdx.x;                 // 0..39999
    int g = node >= N_NODES;
    int ln = node - g * N_NODES;
    const float2* __restrict__ xv = (const float2*)(g ? x2 : x1);
    const int* __restrict__ rp = g_rowptr + g * (N_NODES + 1);
    const int* __restrict__ cs = g_csrsrc + g * N_EDGES;
    int tid = threadIdx.x;
    float2 acc = xv[(size_t)ln * 128 + tid];
    int s = rp[ln], e = rp[ln + 1];
#pragma unroll 4
    for (int i = s; i < e; i++) {
        int sr = cs[i];
        float2 r = xv[(size_t)sr * 128 + tid];
        acc.x += r.x; acc.y += r.y;
    }
    __nv_bfloat16 h0 = __float2bfloat16(acc.x), h1 = __float2bfloat16(acc.y);
    __nv_bfloat16 l0 = __float2bfloat16(acc.x - __bfloat162float(h0));
    __nv_bfloat16 l1 = __float2bfloat16(acc.y - __bfloat162float(h1));
    ((__nv_bfloat162*)(g_ahi + (size_t)node * FIN))[tid] = bpack(h0, h1);
    ((__nv_bfloat162*)(g_alo + (size_t)node * FIN))[tid] = bpack(l0, l1);
}

__global__ __launch_bounds__(128) void agg512_kernel() {
    int node = blockIdx.x;
    int g = node >= N_NODES;
    int ln = node - g * N_NODES;
    const float4* __restrict__ xv = (const float4*)g_x;
    const int* __restrict__ rp = g_rowptr + g * (N_NODES + 1);
    const int* __restrict__ cs = g_csrsrc + g * N_EDGES;
    int tid = threadIdx.x;
    int goff = g * N_NODES;
    float4 acc = xv[(size_t)node * 128 + tid];
    int s = rp[ln], e = rp[ln + 1];
#pragma unroll 4
    for (int i = s; i < e; i++) {
        int sr = cs[i] + goff;
        float4 r = xv[(size_t)sr * 128 + tid];
        acc.x += r.x; acc.y += r.y; acc.z += r.z; acc.w += r.w;
    }
    float f[4] = {acc.x, acc.y, acc.z, acc.w};
    __nv_bfloat16 h[4], l[4];
#pragma unroll
    for (int u = 0; u < 4; u++) {
        h[u] = __float2bfloat16(f[u]);
        l[u] = __float2bfloat16(f[u] - __bfloat162float(h[u]));
    }
    __nv_bfloat162* dh = (__nv_bfloat162*)(g_ahi + (size_t)node * HDIM + tid * 4);
    __nv_bfloat162* dl = (__nv_bfloat162*)(g_alo + (size_t)node * HDIM + tid * 4);
    dh[0] = bpack(h[0], h[1]); dh[1] = bpack(h[2], h[3]);
    dl[0] = bpack(l[0], l[1]); dl[1] = bpack(l[2], l[3]);
}

// ---------------- mma.sync bf16 GEMM: C = relu(A[R,K] @ Wt^T + bias) ---------
// A as (Ahi, Alo) [R,K] bf16; B = Wt [MOUT,K] bf16 (K-major = col-major k x n).
// 3-product split: Ahi*Bhi + Alo*Bhi + Ahi*Blo, fp32 accum.
// Tile: BM=128, BN=64, BK=32; 8 warps (4x2), warp tile 32x32 (2 m x 4 n frags).
#define APAD 40   // 32 + 8 pad; 80B row stride -> conflict-free ldmatrix

__global__ __launch_bounds__(256) void mma_gemm_kernel(
    const __nv_bfloat16* __restrict__ Ahi, const __nv_bfloat16* __restrict__ Alo,
    const __nv_bfloat16* __restrict__ Bhi, const __nv_bfloat16* __restrict__ Blo,
    const float* __restrict__ bias,
    float* __restrict__ Cf,
    __nv_bfloat16* __restrict__ Chi, __nv_bfloat16* __restrict__ Clo,
    int K, int outSplit)
{
    __shared__ __nv_bfloat16 As_hi[128][APAD];
    __shared__ __nv_bfloat16 As_lo[128][APAD];
    __shared__ __nv_bfloat16 Bs_hi[64][APAD];
    __shared__ __nv_bfloat16 Bs_lo[64][APAD];

    int tid = threadIdx.x, wid = tid >> 5, lane = tid & 31;
    int warpM = wid & 3;        // 0..3 -> 32-row slice
    int warpN = wid >> 2;       // 0..1 -> 32-col slice
    int rowBase = blockIdx.x * 128;
    int colBase = blockIdx.y * 64;

    float acc[2][4][4];
#pragma unroll
    for (int i = 0; i < 2; i++)
#pragma unroll
        for (int j = 0; j < 4; j++)
#pragma unroll
            for (int u = 0; u < 4; u++) acc[i][j][u] = 0.f;

    uint32_t aHiB = smem_u32(&As_hi[0][0]);
    uint32_t aLoB = smem_u32(&As_lo[0][0]);
    uint32_t bHiB = smem_u32(&Bs_hi[0][0]);
    uint32_t bLoB = smem_u32(&Bs_lo[0][0]);

    for (int c = 0; c < K; c += 32) {
        // A tile: 128 rows x 32 cols, hi+lo. 512 uint4 per buffer, 2 per thread.
#pragma unroll
        for (int it = 0; it < 2; it++) {
            int idx = it * 256 + tid;         // 0..511
            int row = idx >> 2, seg = idx & 3;
            int ar = rowBase + row;
            uint4 vh, vl;
            if (ar < RTOT) {
                vh = *(const uint4*)(Ahi + (size_t)ar * K + c + seg * 8);
                vl = *(const uint4*)(Alo + (size_t)ar * K + c + seg * 8);
            } else {
                vh = make_uint4(0u, 0u, 0u, 0u);
                vl = vh;
            }
            *(uint4*)&As_hi[row][seg * 8] = vh;
            *(uint4*)&As_lo[row][seg * 8] = vl;
        }
        // B tile: 64 rows x 32 cols, hi+lo. 256 uint4 per buffer, 1 per thread.
        {
            int row = tid >> 2, seg = tid & 3;
            int br = colBase + row;            // < MOUT always
            *(uint4*)&Bs_hi[row][seg * 8] =
                *(const uint4*)(Bhi + (size_t)br * K + c + seg * 8);
            *(uint4*)&Bs_lo[row][seg * 8] =
                *(const uint4*)(Blo + (size_t)br * K + c + seg * 8);
        }
        __syncthreads();

#pragma unroll
        for (int kk = 0; kk < 2; kk++) {
            int k0 = kk * 16;
            uint32_t ah[2][4], al[2][4], bh[4][2], bl[4][2];
#pragma unroll
            for (int i = 0; i < 2; i++) {
                uint32_t off = (uint32_t)((warpM * 32 + i * 16 + (lane & 15)) * APAD
                                          + k0 + (lane >> 4) * 8) * 2;
                LDSM4(ah[i][0], ah[i][1], ah[i][2], ah[i][3], aHiB + off);
                LDSM4(al[i][0], al[i][1], al[i][2], al[i][3], aLoB + off);
            }
#pragma unroll
            for (int j = 0; j < 4; j++) {
                int t = lane & 15;
                uint32_t off = (uint32_t)((warpN * 32 + j * 8 + (t & 7)) * APAD
                                          + k0 + (t >> 3) * 8) * 2;
                LDSM2(bh[j][0], bh[j][1], bHiB + off);
                LDSM2(bl[j][0], bl[j][1], bLoB + off);
            }
#pragma unroll
            for (int i = 0; i < 2; i++)
#pragma unroll
                for (int j = 0; j < 4; j++) {
                    MMA16816(acc[i][j], ah[i], bh[j]);
                    MMA16816(acc[i][j], al[i], bh[j]);
                    MMA16816(acc[i][j], ah[i], bl[j]);
                }
        }
        __syncthreads();
    }

    // epilogue: bias + relu; write fp32 or bf16 hi/lo split
    int quad = lane >> 2, qq = lane & 3;
#pragma unroll
    for (int i = 0; i < 2; i++) {
#pragma unroll
        for (int j = 0; j < 4; j++) {
            int col = colBase + warpN * 32 + j * 8 + qq * 2;
            float bv0 = __ldg(&bias[col]);
            float bv1 = __ldg(&bias[col + 1]);
#pragma unroll
            for (int h = 0; h < 2; h++) {
                int row = rowBase + warpM * 32 + i * 16 + quad + h * 8;
                if (row < RTOT) {
                    float v0 = fmaxf(acc[i][j][h * 2 + 0] + bv0, 0.f);
                    float v1 = fmaxf(acc[i][j][h * 2 + 1] + bv1, 0.f);
                    size_t o = (size_t)row * MOUT + col;
                    if (!outSplit) {
                        *(float2*)(Cf + o) = make_float2(v0, v1);
                    } else {
                        __nv_bfloat16 h0 = __float2bfloat16(v0);
                        __nv_bfloat16 h1 = __float2bfloat16(v1);
                        __nv_bfloat16 l0 = __float2bfloat16(v0 - __bfloat162float(h0));
                        __nv_bfloat16 l1 = __float2bfloat16(v1 - __bfloat162float(h1));
                        *(__nv_bfloat162*)(Chi + o) = bpack(h0, h1);
                        *(__nv_bfloat162*)(Clo + o) = bpack(l0, l1);
                    }
                }
            }
        }
    }
}

// ---------------- final linear [N,512] -> [N,2] ------------------------------
__global__ __launch_bounds__(256) void lin_kernel(const float* __restrict__ x,
                                                  const float* __restrict__ lw,
                                                  const float* __restrict__ lb,
                                                  float* __restrict__ o)
{
    int gw   = (blockIdx.x * blockDim.x + threadIdx.x) >> 5;
    int lane = threadIdx.x & 31;
    if (gw >= N_NODES) return;
    const float* __restrict__ row = x + (size_t)gw * HDIM;
    float a0 = 0.f, a1 = 0.f;
#pragma unroll 4
    for (int k = lane; k < HDIM; k += 32) {
        float v = row[k];
        a0 += v * lw[2 * k];
        a1 += v * lw[2 * k + 1];
    }
#pragma unroll
    for (int off = 16; off; off >>= 1) {
        a0 += __shfl_down_sync(0xffffffffu, a0, off);
        a1 += __shfl_down_sync(0xffffffffu, a1, off);
    }
    if (lane == 0) {
        o[gw * 2 + 0] = a0 + lb[0];
        o[gw * 2 + 1] = a1 + lb[1];
    }
}

// ---------------- pairwise distance ------------------------------------------
__global__ __launch_bounds__(256) void dist_kernel() {
    int i = blockIdx.x * blockDim.x + threadIdx.x;
    if (i >= NSORT) return;
    if (i < N_NODES) {
        float d0 = g_o1[2 * i]     - g_o2[2 * i]     + 1e-6f;
        float d1 = g_o1[2 * i + 1] - g_o2[2 * i + 1] + 1e-6f;
        g_dist[i] = sqrtf(d0 * d0 + d1 * d1);
    } else {
        g_dist[i] = -1.0f;
    }
}

// ---------------- top-k (bitonic) + MLP head, single block -------------------
#define HTHREADS 512

__global__ __launch_bounds__(HTHREADS, 1)
void head_kernel(const float* __restrict__ fc1w, const float* __restrict__ fc1b,
                 const float* __restrict__ ln1g, const float* __restrict__ ln1b,
                 const float* __restrict__ fc2w, const float* __restrict__ fc2b,
                 const float* __restrict__ ln2g, const float* __restrict__ ln2b,
                 const float* __restrict__ fc3w, const float* __restrict__ fc3b,
                 float* __restrict__ out)
{
    extern __shared__ float sm[];
    float* s    = sm;                  // NSORT
    float* red  = sm + NSORT;          // 512
    float* h1   = red + 512;           // 128
    float* h2   = h1 + 128;            // 512
    float* misc = h2 + 512;            // 4

    int tid = threadIdx.x;

    for (int i = tid; i < NSORT; i += HTHREADS) s[i] = g_dist[i];
    __syncthreads();

    for (int k = 2; k <= NSORT; k <<= 1) {
        for (int j = k >> 1; j > 0; j >>= 1) {
            for (int i = tid; i < NSORT; i += HTHREADS) {
                int ixj = i ^ j;
                if (ixj > i) {
                    float a = s[i], b = s[ixj];
                    bool up = ((i & k) == 0);
                    if (up ? (a > b) : (a < b)) { s[i] = b; s[ixj] = a; }
                }
            }
            __syncthreads();
        }
    }

    {
        int part = tid >> 7;   // 0..3
        int j    = tid & 127;
        float acc = 0.f;
        for (int r = part; r < KTOP; r += 4)
            acc += s[NSORT - 1 - r] * fc1w[r * 128 + j];
        red[part * 128 + j] = acc;
    }
    __syncthreads();
    if (tid < 128) {
        float v = fc1b[tid];
        for (int p = 0; p < 4; p++) v += red[p * 128 + tid];
        h1[tid] = v;
    }
    __syncthreads();
    if (tid == 0) {
        float m = 0.f;
        for (int i = 0; i < 128; i++) m += h1[i];
        m /= 128.f;
        float v = 0.f;
        for (int i = 0; i < 128; i++) { float d = h1[i] - m; v += d * d; }
        v /= 128.f;
        misc[0] = m;
        misc[1] = rsqrtf(v + 1e-5f);
    }
    __syncthreads();
    if (tid < 128) {
        float v = (h1[tid] - misc[0]) * misc[1] * ln1g[tid] + ln1b[tid];
        h1[tid] = fmaxf(v, 0.f);
    }
    __syncthreads();

    {
        float acc = fc2b[tid];
        for (int k = 0; k < 128; k++) acc += h1[k] * fc2w[k * 512 + tid];
        h2[tid] = acc;
    }
    __syncthreads();
    if (tid == 0) {
        float m = 0.f;
        for (int i = 0; i < 512; i++) m += h2[i];
        m /= 512.f;
        float v = 0.f;
        for (int i = 0; i < 512; i++) { float d = h2[i] - m; v += d * d; }
        v /= 512.f;
        misc[0] = m;
        misc[1] = rsqrtf(v + 1e-5f);
    }
    __syncthreads();
    {
        float v = (h2[tid] - misc[0]) * misc[1] * ln2g[tid] + ln2b[tid];
        red[tid] = fmaxf(v, 0.f) * fc3w[tid];
    }
    __syncthreads();
    if (tid == 0) {
        float z = fc3b[0];
        for (int i = 0; i < 512; i++) z += red[i];
        out[0] = 1.f / (1.f + expf(-z));
    }
}

// ---------------- launcher ---------------------------------------------------
extern "C" void kernel_launch(void* const* d_in, const int* in_sizes, int n_in,
                              void* d_out, int out_size)
{
    (void)in_sizes; (void)n_in; (void)out_size;
    const float* x1   = (const float*)d_in[0];
    const int*   ei1  = (const int*)  d_in[1];
    const float* x2   = (const float*)d_in[2];
    const int*   ei2  = (const int*)  d_in[3];
    const float* w11  = (const float*)d_in[4];
    const float* b11  = (const float*)d_in[5];
    const float* w12  = (const float*)d_in[6];
    const float* b12  = (const float*)d_in[7];
    const float* w21  = (const float*)d_in[8];
    const float* b21  = (const float*)d_in[9];
    const float* w22  = (const float*)d_in[10];
    const float* b22  = (const float*)d_in[11];
    const float* w31  = (const float*)d_in[12];
    const float* b31  = (const float*)d_in[13];
    const float* w32  = (const float*)d_in[14];
    const float* b32  = (const float*)d_in[15];
    const float* linw = (const float*)d_in[16];
    const float* linb = (const float*)d_in[17];
    const float* fc1w = (const float*)d_in[18];
    const float* fc1b = (const float*)d_in[19];
    const float* ln1g = (const float*)d_in[20];
    const float* ln1b = (const float*)d_in[21];
    const float* fc2w = (const float*)d_in[22];
    const float* fc2b = (const float*)d_in[23];
    const float* ln2g = (const float*)d_in[24];
    const float* ln2b = (const float*)d_in[25];
    const float* fc3w = (const float*)d_in[26];
    const float* fc3b = (const float*)d_in[27];
    float* out = (float*)d_out;

    float *p_x, *p_o1, *p_o2;
    __nv_bfloat16 *p_ahi, *p_alo, *p_thi, *p_tlo, *p_whi, *p_wlo;
    cudaGetSymbolAddress((void**)&p_x,   g_x);
    cudaGetSymbolAddress((void**)&p_o1,  g_o1);
    cudaGetSymbolAddress((void**)&p_o2,  g_o2);
    cudaGetSymbolAddress((void**)&p_ahi, g_ahi);
    cudaGetSymbolAddress((void**)&p_alo, g_alo);
    cudaGetSymbolAddress((void**)&p_thi, g_thi);
    cudaGetSymbolAddress((void**)&p_tlo, g_tlo);
    cudaGetSymbolAddress((void**)&p_whi, g_whi);
    cudaGetSymbolAddress((void**)&p_wlo, g_wlo);

    const size_t O11 = 0;
    const size_t O12 = 512 * 256;
    const size_t O21 = O12 + 512 * 512;
    const size_t O22 = O21 + 512 * 512;
    const size_t O31 = O22 + 512 * 512;
    const size_t O32 = O31 + 512 * 512;

    int eblk = (N_EDGES + 255) / 256;
    int nblk = (N_NODES + 255) / 256;
    int wblk512 = (512 * 512 + 255) / 256;
    int wblk256 = (512 * 256 + 255) / 256;

    wprep_kernel<<<wblk256, 256>>>(w11, 256, 512, p_whi + O11, p_wlo + O11);
    wprep_kernel<<<wblk512, 256>>>(w12, 512, 512, p_whi + O12, p_wlo + O12);
    wprep_kernel<<<wblk512, 256>>>(w21, 512, 512, p_whi + O21, p_wlo + O21);
    wprep_kernel<<<wblk512, 256>>>(w22, 512, 512, p_whi + O22, p_wlo + O22);
    wprep_kernel<<<wblk512, 256>>>(w31, 512, 512, p_whi + O31, p_wlo + O31);
    wprep_kernel<<<wblk512, 256>>>(w32, 512, 512, p_whi + O32, p_wlo + O32);

    const int* EIs[2] = {ei1, ei2};
    for (int g = 0; g < 2; g++) {
        const int* src = EIs[g];
        const int* dst = EIs[g] + N_EDGES;
        zero_deg_kernel<<<nblk, 256>>>();
        hist_kernel<<<eblk, 256>>>(dst);
        scan_kernel<<<1, 256>>>(g);
        fill_kernel<<<eblk, 256>>>(src, dst, g);
    }

    dim3 ggrid((RTOT + 127) / 128, MOUT / 64);

    // layer 1 (K=256)
    agg256_kernel<<<RTOT, 128>>>(x1, x2);
    mma_gemm_kernel<<<ggrid, 256>>>(p_ahi, p_alo, p_whi + O11, p_wlo + O11, b11,
                                    nullptr, p_thi, p_tlo, 256, 1);
    mma_gemm_kernel<<<ggrid, 256>>>(p_thi, p_tlo, p_whi + O12, p_wlo + O12, b12,
                                    p_x, nullptr, nullptr, 512, 0);
    // layer 2
    agg512_kernel<<<RTOT, 128>>>();
    mma_gemm_kernel<<<ggrid, 256>>>(p_ahi, p_alo, p_whi + O21, p_wlo + O21, b21,
                                    nullptr, p_thi, p_tlo, 512, 1);
    mma_gemm_kernel<<<ggrid, 256>>>(p_thi, p_tlo, p_whi + O22, p_wlo + O22, b22,
                                    p_x, nullptr, nullptr, 512, 0);
    // layer 3
    agg512_kernel<<<RTOT, 128>>>();
    mma_gemm_kernel<<<ggrid, 256>>>(p_ahi, p_alo, p_whi + O31, p_wlo + O31, b31,
                                    nullptr, p_thi, p_tlo, 512, 1);
    mma_gemm_kernel<<<ggrid, 256>>>(p_thi, p_tlo, p_whi + O32, p_wlo + O32, b32,
                                    p_x, nullptr, nullptr, 512, 0);

    lin_kernel<<<(N_NODES * 32 + 255) / 256, 256>>>(p_x, linw, linb, p_o1);
    lin_kernel<<<(N_NODES * 32 + 255) / 256, 256>>>(p_x + (size_t)N_NODES * HDIM, linw, linb, p_o2);

    dist_kernel<<<NSORT / 256, 256>>>();

    const int SMEM_HEAD = (NSORT + 512 + 128 + 512 + 8) * (int)sizeof(float);
    cudaFuncSetAttribute(head_kernel, cudaFuncAttributeMaxDynamicSharedMemorySize, SMEM_HEAD);
    head_kernel<<<1, HTHREADS, SMEM_HEAD>>>(fc1w, fc1b, ln1g, ln1b,
                                            fc2w, fc2b, ln2g, ln2b,
                                            fc3w, fc3b, out);
}